// round 15
// baseline (speedup 1.0000x reference)
#include <cuda_runtime.h>
#include <cuda_fp16.h>
#include <cstdint>
#include <cmath>

// Problem constants (fixed by setup_inputs)
#define B_   8
#define NQ_  8192
#define E_   256
#define HN_  8
#define P_   4
#define DH_  32
#define NV_  16384   // 128*128
#define WL_  128
#define HL_  128

// Scratch (no cudaMalloc allowed)
__device__ __half g_v [(size_t)B_ * NV_ * E_];           // projected value, fp16
__device__ float  g_oa[(size_t)B_ * NQ_ * 96];           // [off(64) | attn(32)] per query
__device__ __half g_o [(size_t)B_ * NQ_ * E_];           // sampled output, fp16
__device__ __half g_wv16[E_ * E_];                       // W_val  fp16 [k][n]
__device__ __half g_wu16[E_ * E_];                       // W_out  fp16 [k][n]
__device__ __half g_wc16[E_ * 96];                       // [W_off|W_attn] fp16 [k][n]
__device__ float  g_bcat[96];

// ---------------------------------------------------------------------------
// PTX helpers
// ---------------------------------------------------------------------------
#define CP_ASYNC16(saddr, gaddr) \
    asm volatile("cp.async.cg.shared.global [%0], [%1], 16;" :: "r"(saddr), "l"(gaddr) : "memory")
#define CP_COMMIT() asm volatile("cp.async.commit_group;" ::: "memory")
template<int N>
__device__ __forceinline__ void cp_wait() {
    asm volatile("cp.async.wait_group %0;" :: "n"(N) : "memory");
}

__device__ __forceinline__ uint32_t smem_u32(const void* p) {
    uint32_t a;
    asm("{ .reg .u64 t; cvta.to.shared.u64 t, %1; cvt.u32.u64 %0, t; }" : "=r"(a) : "l"(p));
    return a;
}

__device__ __forceinline__ uint32_t pack_h2(float x, float y) {
    uint32_t r;
    asm("cvt.rn.f16x2.f32 %0, %2, %1;" : "=r"(r) : "f"(x), "f"(y));
    return r;
}

#define LDMATRIX_X4(r, addr) \
    asm volatile("ldmatrix.sync.aligned.m8n8.x4.shared.b16 {%0,%1,%2,%3}, [%4];" \
        : "=r"((r)[0]), "=r"((r)[1]), "=r"((r)[2]), "=r"((r)[3]) : "r"(addr))
#define LDMATRIX_X4_T(r, addr) \
    asm volatile("ldmatrix.sync.aligned.m8n8.x4.trans.shared.b16 {%0,%1,%2,%3}, [%4];" \
        : "=r"((r)[0]), "=r"((r)[1]), "=r"((r)[2]), "=r"((r)[3]) : "r"(addr))
#define STS_V2(addr, x, y) \
    asm volatile("st.shared.v2.b32 [%0], {%1,%2};" :: "r"(addr), "r"(x), "r"(y) : "memory")

__device__ __forceinline__ void mma_f16(float d[4], const uint32_t a[4],
                                        uint32_t b0, uint32_t b1) {
    asm volatile(
        "mma.sync.aligned.m16n8k16.row.col.f32.f16.f16.f32 "
        "{%0,%1,%2,%3}, {%4,%5,%6,%7}, {%8,%9}, {%0,%1,%2,%3};"
        : "+f"(d[0]), "+f"(d[1]), "+f"(d[2]), "+f"(d[3])
        : "r"(a[0]), "r"(a[1]), "r"(a[2]), "r"(a[3]), "r"(b0), "r"(b1));
}

// ---------------------------------------------------------------------------
// Wide GEMM: C(M,256) = A(M,256) @ Wh(256,256) + bias (+R)
// 512 threads, BM=128, BN=256, 3-stage cp.async ring (R8 best config).
// ---------------------------------------------------------------------------
template<bool AHALF, bool RESID, bool OHALF>
__global__ __launch_bounds__(512, 1)
void gemm_wide(const void* __restrict__ Av, const __half* __restrict__ Wh,
               const float* __restrict__ bias, const float* __restrict__ R,
               void* __restrict__ Cv, int M)
{
    constexpr int N = 256;
    constexpr int BM = 128, BK = 32, NIT = E_ / BK;  // 8
    constexpr int ST = 3;
    constexpr int AP = BK + 8;        // 40 halves
    constexpr int BP = 256 + 8;       // 264 halves
    constexpr int ASZ = BM * AP;      // 5120 halves
    constexpr int BSZ = BK * BP;      // 8448 halves

    extern __shared__ __half hs[];

    const int tid  = threadIdx.x;
    const int wid  = tid >> 5;
    const int lane = tid & 31;
    const int gid  = lane >> 2;
    const int tig  = lane & 3;

    const int row0 = blockIdx.x * BM;
    const int wr0  = (wid & 3) * 32;
    const int wc0  = (wid >> 2) * 64;

    const uint32_t sbase = smem_u32(hs);
    uint32_t sA[ST], sB[ST];
#pragma unroll
    for (int s = 0; s < ST; s++) {
        sA[s] = sbase + (uint32_t)(s * (ASZ + BSZ)) * 2;
        sB[s] = sA[s] + (uint32_t)ASZ * 2;
    }

    const float*  Af = (const float*)Av;
    const __half* Ah = (const __half*)Av;

    float acc[2][8][4];
#pragma unroll
    for (int mt = 0; mt < 2; mt++)
#pragma unroll
        for (int nt = 0; nt < 8; nt++)
#pragma unroll
            for (int i = 0; i < 4; i++) acc[mt][nt][i] = 0.f;

    float4 ar[2];

    auto ldgA = [&](int k0) {
        if (!AHALF) {
#pragma unroll
            for (int i = 0; i < 2; i++) {
                int idx = tid + i * 512;
                int r = idx >> 3, c4 = idx & 7;
                ar[i] = *(const float4*)&Af[(size_t)(row0 + r) * E_ + k0 + c4 * 4];
            }
        }
    };
    auto stsA = [&](int s) {
        if (!AHALF) {
#pragma unroll
            for (int i = 0; i < 2; i++) {
                int idx = tid + i * 512;
                int r = idx >> 3, c4 = idx & 7;
                STS_V2(sA[s] + (uint32_t)(r * AP + c4 * 4) * 2,
                       pack_h2(ar[i].x, ar[i].y), pack_h2(ar[i].z, ar[i].w));
            }
        }
    };
    auto asyncA = [&](int s, int k0) {
        if (AHALF) {
            int r = tid >> 2, c8 = tid & 3;
            CP_ASYNC16(sA[s] + (uint32_t)(r * AP + c8 * 8) * 2,
                       Ah + (size_t)(row0 + r) * E_ + k0 + c8 * 8);
        }
    };
    auto asyncB = [&](int s, int k0) {
#pragma unroll
        for (int i = 0; i < 2; i++) {
            int chunk = tid + i * 512;
            int r = chunk >> 5, c8 = chunk & 31;
            CP_ASYNC16(sB[s] + (uint32_t)(r * BP + c8 * 8) * 2,
                       Wh + (size_t)(k0 + r) * N + c8 * 8);
        }
    };

    auto compute = [&](int s) {
#pragma unroll
        for (int ks = 0; ks < 2; ks++) {
            uint32_t a0[4], a1[4];
            const uint32_t arow = (uint32_t)(lane & 15);
            const uint32_t kof  = (uint32_t)(ks * 16 + (lane >> 4) * 8);
            LDMATRIX_X4(a0, sA[s] + (uint32_t)((wr0 + arow) * AP + kof) * 2);
            LDMATRIX_X4(a1, sA[s] + (uint32_t)((wr0 + 16 + arow) * AP + kof) * 2);
#pragma unroll
            for (int ntp = 0; ntp < 4; ntp++) {
                uint32_t bb[4];
                LDMATRIX_X4_T(bb, sB[s] + (uint32_t)((ks * 16 + (lane & 15)) * BP
                                   + wc0 + ntp * 16 + (lane >> 4) * 8) * 2);
                mma_f16(acc[0][2 * ntp],     a0, bb[0], bb[1]);
                mma_f16(acc[1][2 * ntp],     a1, bb[0], bb[1]);
                mma_f16(acc[0][2 * ntp + 1], a0, bb[2], bb[3]);
                mma_f16(acc[1][2 * ntp + 1], a1, bb[2], bb[3]);
            }
        }
    };

    // ---- prologue ----
    ldgA(0);
    asyncA(0, 0); asyncB(0, 0); CP_COMMIT();
    stsA(0);
    ldgA(BK);
    asyncA(1, BK); asyncB(1, BK); CP_COMMIT();
    stsA(1);
    ldgA(2 * BK);

    // ---- mainloop ----
#pragma unroll
    for (int it = 0; it < NIT; it++) {
        if (it == NIT - 1) cp_wait<0>(); else cp_wait<1>();
        __syncthreads();
        if (it + 2 < NIT) {
            const int s2 = (it + 2) % ST;
            stsA(s2);
            asyncA(s2, (it + 2) * BK);
            asyncB(s2, (it + 2) * BK);
            CP_COMMIT();
            if (it + 3 < NIT) ldgA((it + 3) * BK);
        }
        compute(it % ST);
    }

    // ---- epilogue ----
    float*   Cf = (float*)Cv;
    __half2* Ch = (__half2*)Cv;
#pragma unroll
    for (int mt = 0; mt < 2; mt++) {
#pragma unroll
        for (int nt = 0; nt < 8; nt++) {
            const int c = wc0 + nt * 8 + 2 * tig;
            const float bx = bias[c], by = bias[c + 1];
            const int r0 = row0 + wr0 + mt * 16 + gid;
            float2 o0 = { acc[mt][nt][0] + bx, acc[mt][nt][1] + by };
            float2 o1 = { acc[mt][nt][2] + bx, acc[mt][nt][3] + by };
            if (RESID) {
                const float2 rv0 = *(const float2*)&R[(size_t)r0 * N + c];
                const float2 rv1 = *(const float2*)&R[(size_t)(r0 + 8) * N + c];
                o0.x += rv0.x; o0.y += rv0.y;
                o1.x += rv1.x; o1.y += rv1.y;
            }
            if (OHALF) {
                Ch[((size_t)r0 * N + c) >> 1]       = __floats2half2_rn(o0.x, o0.y);
                Ch[((size_t)(r0 + 8) * N + c) >> 1] = __floats2half2_rn(o1.x, o1.y);
            } else {
                *(float2*)&Cf[(size_t)r0 * N + c]       = o0;
                *(float2*)&Cf[(size_t)(r0 + 8) * N + c] = o1;
            }
        }
    }
}

// ---------------------------------------------------------------------------
// Narrow GEMM (off/attn proj): 256 threads, BM=128, BN=96, 3-stage
// ---------------------------------------------------------------------------
__global__ __launch_bounds__(256, 2)
void gemm_oa(const float* __restrict__ A, const __half* __restrict__ Wh,
             const float* __restrict__ bias, float* __restrict__ C, int M)
{
    constexpr int N = 96;
    constexpr int BM = 128, BN = 96, BK = 32, NIT = E_ / BK;
    constexpr int ST = 3;
    constexpr int AP = BK + 8;
    constexpr int BP = BN + 8;
    constexpr int ASZ = BM * AP;
    constexpr int BSZ = BK * BP;
    constexpr int NTP = BN / 32;

    __shared__ __half hs[ST * (ASZ + BSZ)];

    const int tid  = threadIdx.x;
    const int wid  = tid >> 5;
    const int lane = tid & 31;
    const int gid  = lane >> 2;
    const int tig  = lane & 3;

    const int row0 = blockIdx.x * BM;
    const int wr0  = (wid & 3) * 32;
    const int wc0  = (wid >> 2) * (BN / 2);

    const uint32_t sbase = smem_u32(hs);
    uint32_t sA[ST], sB[ST];
#pragma unroll
    for (int s = 0; s < ST; s++) {
        sA[s] = sbase + (uint32_t)(s * (ASZ + BSZ)) * 2;
        sB[s] = sA[s] + (uint32_t)ASZ * 2;
    }

    float acc[2][BN / 16][4];
#pragma unroll
    for (int mt = 0; mt < 2; mt++)
#pragma unroll
        for (int nt = 0; nt < BN / 16; nt++)
#pragma unroll
            for (int i = 0; i < 4; i++) acc[mt][nt][i] = 0.f;

    float4 ar[4];

    auto ldgA = [&](int k0) {
#pragma unroll
        for (int i = 0; i < 4; i++) {
            int idx = tid + i * 256;
            int r = idx >> 3, c4 = idx & 7;
            ar[i] = *(const float4*)&A[(size_t)(row0 + r) * E_ + k0 + c4 * 4];
        }
    };
    auto stsA = [&](int s) {
#pragma unroll
        for (int i = 0; i < 4; i++) {
            int idx = tid + i * 256;
            int r = idx >> 3, c4 = idx & 7;
            STS_V2(sA[s] + (uint32_t)(r * AP + c4 * 4) * 2,
                   pack_h2(ar[i].x, ar[i].y), pack_h2(ar[i].z, ar[i].w));
        }
    };
    auto asyncB = [&](int s, int k0) {
        constexpr int BCH = BK * BN / 8;   // 384
#pragma unroll
        for (int i = 0; i < 2; i++) {
            int chunk = tid + i * 256;
            if (chunk < BCH) {
                int r = chunk / (BN / 8), c8 = chunk % (BN / 8);
                CP_ASYNC16(sB[s] + (uint32_t)(r * BP + c8 * 8) * 2,
                           Wh + (size_t)(k0 + r) * N + c8 * 8);
            }
        }
    };

    auto compute = [&](int s) {
#pragma unroll
        for (int ks = 0; ks < 2; ks++) {
            uint32_t a0[4], a1[4];
            const uint32_t arow = (uint32_t)(lane & 15);
            const uint32_t kof  = (uint32_t)(ks * 16 + (lane >> 4) * 8);
            LDMATRIX_X4(a0, sA[s] + (uint32_t)((wr0 + arow) * AP + kof) * 2);
            LDMATRIX_X4(a1, sA[s] + (uint32_t)((wr0 + 16 + arow) * AP + kof) * 2);
#pragma unroll
            for (int ntp = 0; ntp < NTP; ntp++) {
                uint32_t bb[4];
                LDMATRIX_X4_T(bb, sB[s] + (uint32_t)((ks * 16 + (lane & 15)) * BP
                                   + wc0 + ntp * 16 + (lane >> 4) * 8) * 2);
                mma_f16(acc[0][2 * ntp],     a0, bb[0], bb[1]);
                mma_f16(acc[1][2 * ntp],     a1, bb[0], bb[1]);
                mma_f16(acc[0][2 * ntp + 1], a0, bb[2], bb[3]);
                mma_f16(acc[1][2 * ntp + 1], a1, bb[2], bb[3]);
            }
        }
    };

    ldgA(0);
    asyncB(0, 0); CP_COMMIT();
    stsA(0);
    ldgA(BK);
    asyncB(1, BK); CP_COMMIT();
    stsA(1);
    ldgA(2 * BK);

#pragma unroll
    for (int it = 0; it < NIT; it++) {
        if (it == NIT - 1) cp_wait<0>(); else cp_wait<1>();
        __syncthreads();
        if (it + 2 < NIT) {
            const int s2 = (it + 2) % ST;
            stsA(s2);
            asyncB(s2, (it + 2) * BK);
            CP_COMMIT();
            if (it + 3 < NIT) ldgA((it + 3) * BK);
        }
        compute(it % ST);
    }

#pragma unroll
    for (int mt = 0; mt < 2; mt++) {
#pragma unroll
        for (int nt = 0; nt < BN / 16; nt++) {
            const int c = wc0 + nt * 8 + 2 * tig;
            const float bx = bias[c], by = bias[c + 1];
            const int r0 = row0 + wr0 + mt * 16 + gid;
            *(float2*)&C[(size_t)r0 * N + c] =
                make_float2(acc[mt][nt][0] + bx, acc[mt][nt][1] + by);
            *(float2*)&C[(size_t)(r0 + 8) * N + c] =
                make_float2(acc[mt][nt][2] + bx, acc[mt][nt][3] + by);
        }
    }
}

// ---------------------------------------------------------------------------
// Weight prep
// ---------------------------------------------------------------------------
__global__ void prep_weights(const float* __restrict__ Wv, const float* __restrict__ Wu,
                             const float* __restrict__ Wo, const float* __restrict__ Wa,
                             const float* __restrict__ bo, const float* __restrict__ ba)
{
    const int t = blockIdx.x * blockDim.x + threadIdx.x;
    if (t < E_ * E_) {
        g_wv16[t] = __float2half_rn(Wv[t]);
        g_wu16[t] = __float2half_rn(Wu[t]);
    }
    if (t < E_ * 96) {
        const int k = t / 96, n = t % 96;
        g_wc16[t] = __float2half_rn(n < 64 ? Wo[k * 64 + n] : Wa[k * 32 + (n - 64)]);
    }
    if (t < 96) g_bcat[t] = (t < 64) ? bo[t] : ba[t - 64];
}

// ---------------------------------------------------------------------------
// Sampling: ONE warp per (b,q) with batch offset; lane = 8 channels.
// ---------------------------------------------------------------------------
__global__ __launch_bounds__(256)
void sample_kernel(const float* __restrict__ ref2d, int bq0)
{
    const int gtid = blockIdx.x * blockDim.x + threadIdx.x;
    const int bq   = bq0 + (gtid >> 5);
    const int lane = gtid & 31;
    const int b = bq >> 13;                     // NQ_ = 8192

    const int h  = lane >> 2;                   // head 0..7
    const int c0 = h * DH_ + (lane & 3) * 8;    // channel base (8 ch)

    const float rxs = fmaf(ref2d[(size_t)bq * 2 + 0], 128.f, -0.5f);
    const float rys = fmaf(ref2d[(size_t)bq * 2 + 1], 128.f, -0.5f);

    const float* qa = g_oa + (size_t)bq * 96;
    const float4 lg = *(const float4*)&qa[64 + h * 4];
    const float e0 = __expf(lg.x), e1 = __expf(lg.y),
                e2 = __expf(lg.z), e3 = __expf(lg.w);
    const float inv = __frcp_rn(e0 + e1 + e2 + e3);
    const float aw[P_] = { e0 * inv, e1 * inv, e2 * inv, e3 * inv };

    const float4 of0 = *(const float4*)&qa[h * 8];
    const float4 of1 = *(const float4*)&qa[h * 8 + 4];
    const float ox[P_] = { of0.x, of0.z, of1.x, of1.z };
    const float oy[P_] = { of0.y, of0.w, of1.y, of1.w };

    const char* vb = (const char*)(g_v + (size_t)b * NV_ * E_ + c0);

    float acc[8] = {0.f, 0.f, 0.f, 0.f, 0.f, 0.f, 0.f, 0.f};
#pragma unroll
    for (int p = 0; p < P_; p++) {
        const float x = rxs + ox[p];
        const float y = rys + oy[p];
        const float x0f = floorf(x), y0f = floorf(y);
        const int x0 = (int)x0f, y0 = (int)y0f;
        const int x1 = x0 + 1,  y1 = y0 + 1;
        const float wx1 = x - x0f, wx0 = 1.f - wx1;
        const float wy1 = y - y0f, wy0 = 1.f - wy1;

        const bool okx0 = (unsigned)x0 < (unsigned)WL_;
        const bool okx1 = (unsigned)x1 < (unsigned)WL_;
        const bool oky0 = (unsigned)y0 < (unsigned)HL_;
        const bool oky1 = (unsigned)y1 < (unsigned)HL_;
        const uint32_t bx0 = (uint32_t)min(max(x0, 0), WL_ - 1) << 9;
        const uint32_t bx1 = (uint32_t)min(max(x1, 0), WL_ - 1) << 9;
        const uint32_t by0 = (uint32_t)min(max(y0, 0), HL_ - 1) << 16;
        const uint32_t by1 = (uint32_t)min(max(y1, 0), HL_ - 1) << 16;

        const float awx0 = aw[p] * wx0, awx1 = aw[p] * wx1;
        const float    ws[4] = { (okx0 & oky0) ? awx0 * wy0 : 0.f,
                                 (okx1 & oky0) ? awx1 * wy0 : 0.f,
                                 (okx0 & oky1) ? awx0 * wy1 : 0.f,
                                 (okx1 & oky1) ? awx1 * wy1 : 0.f };
        const uint32_t os[4] = { by0 + bx0, by0 + bx1, by1 + bx0, by1 + bx1 };

#pragma unroll
        for (int cnr = 0; cnr < 4; cnr++) {
            const float w = ws[cnr];
            const uint4 raw = *(const uint4*)(vb + os[cnr]);
            const float2 f0 = __half22float2(*(const __half2*)&raw.x);
            const float2 f1 = __half22float2(*(const __half2*)&raw.y);
            const float2 f2 = __half22float2(*(const __half2*)&raw.z);
            const float2 f3 = __half22float2(*(const __half2*)&raw.w);
            acc[0] = fmaf(w, f0.x, acc[0]); acc[1] = fmaf(w, f0.y, acc[1]);
            acc[2] = fmaf(w, f1.x, acc[2]); acc[3] = fmaf(w, f1.y, acc[3]);
            acc[4] = fmaf(w, f2.x, acc[4]); acc[5] = fmaf(w, f2.y, acc[5]);
            acc[6] = fmaf(w, f3.x, acc[6]); acc[7] = fmaf(w, f3.y, acc[7]);
        }
    }

    uint4 outp;
    outp.x = pack_h2(acc[0], acc[1]);
    outp.y = pack_h2(acc[2], acc[3]);
    outp.z = pack_h2(acc[4], acc[5]);
    outp.w = pack_h2(acc[6], acc[7]);
    *(uint4*)&g_o[(size_t)bq * E_ + c0] = outp;
}

// ---------------------------------------------------------------------------
extern "C" void kernel_launch(void* const* d_in, const int* in_sizes, int n_in,
                              void* d_out, int out_size)
{
    const float* query  = (const float*)d_in[0];
    const float* value  = (const float*)d_in[1];
    const float* ref2d  = (const float*)d_in[2];
    const float* W_off  = (const float*)d_in[4];
    const float* b_off  = (const float*)d_in[5];
    const float* W_attn = (const float*)d_in[6];
    const float* b_attn = (const float*)d_in[7];
    const float* W_val  = (const float*)d_in[8];
    const float* b_val  = (const float*)d_in[9];
    const float* W_out  = (const float*)d_in[10];
    const float* b_out  = (const float*)d_in[11];
    float* out = (float*)d_out;

    void *v_ptr, *oa_ptr, *o_ptr, *wv_ptr, *wu_ptr, *wc_ptr, *bc_ptr;
    cudaGetSymbolAddress(&v_ptr,  g_v);
    cudaGetSymbolAddress(&oa_ptr, g_oa);
    cudaGetSymbolAddress(&o_ptr,  g_o);
    cudaGetSymbolAddress(&wv_ptr, g_wv16);
    cudaGetSymbolAddress(&wu_ptr, g_wu16);
    cudaGetSymbolAddress(&wc_ptr, g_wc16);
    cudaGetSymbolAddress(&bc_ptr, g_bcat);

    // one-time side stream + events (host objects; created outside capture
    // on the first/correctness call, reused thereafter)
    static cudaStream_t s2 = nullptr;
    static cudaEvent_t  eP = nullptr;
    static cudaEvent_t  ev[B_];
    if (!s2) {
        cudaStreamCreateWithFlags(&s2, cudaStreamNonBlocking);
        cudaEventCreateWithFlags(&eP, cudaEventDisableTiming);
        for (int b = 0; b < B_; b++)
            cudaEventCreateWithFlags(&ev[b], cudaEventDisableTiming);
    }

    const int wide_smem = 3 * (128 * 40 + 32 * 264) * 2;   // 81408 B
    cudaFuncSetAttribute((const void*)gemm_wide<false, false, true>,
                         cudaFuncAttributeMaxDynamicSharedMemorySize, wide_smem);
    cudaFuncSetAttribute((const void*)gemm_wide<true, true, false>,
                         cudaFuncAttributeMaxDynamicSharedMemorySize, wide_smem);

    const int Mq = B_ * NQ_;   // 65536

    // 0) weight prep on the capture (default) stream
    prep_weights<<<256, 256>>>(W_val, W_out, W_off, W_attn, b_off, b_attn);

    // fork: side stream runs per-batch value projections
    cudaEventRecord(eP, 0);
    cudaStreamWaitEvent(s2, eP, 0);
    for (int b = 0; b < B_; b++) {
        const float* Ab = value + (size_t)b * NV_ * E_;
        __half* Cb = (__half*)v_ptr + (size_t)b * NV_ * E_;
        gemm_wide<false, false, true><<<NV_ / 128, 512, wide_smem, s2>>>(
            Ab, (const __half*)wv_ptr, b_val, nullptr, Cb, NV_);
        cudaEventRecord(ev[b], s2);
    }

    // default stream: fused offset+attn projection (overlaps early vproj)
    gemm_oa<<<Mq / 128, 256>>>(query, (const __half*)wc_ptr,
                               (const float*)bc_ptr, (float*)oa_ptr, Mq);

    // per batch: join vproj_b, then sample_b + outproj_b (overlaps later vproj)
    for (int b = 0; b < B_; b++) {
        cudaStreamWaitEvent(0, ev[b], 0);
        sample_kernel<<<(NQ_ * 32) / 256, 256>>>(ref2d, b * NQ_);
        const __half* Ob = (const __half*)o_ptr + (size_t)b * NQ_ * E_;
        gemm_wide<true, true, false><<<NQ_ / 128, 512, wide_smem>>>(
            Ob, (const __half*)wu_ptr, b_out,
            query + (size_t)b * NQ_ * E_, out + (size_t)b * NQ_ * E_, NQ_);
    }
}

// round 16
// speedup vs baseline: 1.2023x; 1.2023x over previous
#include <cuda_runtime.h>
#include <cuda_fp16.h>
#include <cstdint>
#include <cmath>

// Problem constants (fixed by setup_inputs)
#define B_   8
#define NQ_  8192
#define E_   256
#define HN_  8
#define P_   4
#define DH_  32
#define NV_  16384   // 128*128
#define WL_  128
#define HL_  128

// Scratch (no cudaMalloc allowed)
__device__ __half g_v [(size_t)B_ * NV_ * E_];           // projected value, fp16
__device__ float  g_oa[(size_t)B_ * NQ_ * 96];           // [off(64) | attn(32)] per query
__device__ __half g_wv16[E_ * E_];                       // W_val  fp16 [k][n]
__device__ __half g_wu16[E_ * E_];                       // W_out  fp16 [k][n]
__device__ __half g_wc16[E_ * 96];                       // [W_off|W_attn] fp16 [k][n]
__device__ float  g_bcat[96];

// ---------------------------------------------------------------------------
// PTX helpers
// ---------------------------------------------------------------------------
#define CP_ASYNC16(saddr, gaddr) \
    asm volatile("cp.async.cg.shared.global [%0], [%1], 16;" :: "r"(saddr), "l"(gaddr) : "memory")
#define CP_COMMIT() asm volatile("cp.async.commit_group;" ::: "memory")
template<int N>
__device__ __forceinline__ void cp_wait() {
    asm volatile("cp.async.wait_group %0;" :: "n"(N) : "memory");
}

__device__ __forceinline__ uint32_t smem_u32(const void* p) {
    uint32_t a;
    asm("{ .reg .u64 t; cvta.to.shared.u64 t, %1; cvt.u32.u64 %0, t; }" : "=r"(a) : "l"(p));
    return a;
}

__device__ __forceinline__ uint32_t pack_h2(float x, float y) {
    uint32_t r;
    asm("cvt.rn.f16x2.f32 %0, %2, %1;" : "=r"(r) : "f"(x), "f"(y));
    return r;
}

#define LDMATRIX_X4(r, addr) \
    asm volatile("ldmatrix.sync.aligned.m8n8.x4.shared.b16 {%0,%1,%2,%3}, [%4];" \
        : "=r"((r)[0]), "=r"((r)[1]), "=r"((r)[2]), "=r"((r)[3]) : "r"(addr))
#define LDMATRIX_X4_T(r, addr) \
    asm volatile("ldmatrix.sync.aligned.m8n8.x4.trans.shared.b16 {%0,%1,%2,%3}, [%4];" \
        : "=r"((r)[0]), "=r"((r)[1]), "=r"((r)[2]), "=r"((r)[3]) : "r"(addr))
#define STS_V2(addr, x, y) \
    asm volatile("st.shared.v2.b32 [%0], {%1,%2};" :: "r"(addr), "r"(x), "r"(y) : "memory")
#define STS_V4(addr, a, b, c, d) \
    asm volatile("st.shared.v4.b32 [%0], {%1,%2,%3,%4};" \
        :: "r"(addr), "r"(a), "r"(b), "r"(c), "r"(d) : "memory")

__device__ __forceinline__ void mma_f16(float d[4], const uint32_t a[4],
                                        uint32_t b0, uint32_t b1) {
    asm volatile(
        "mma.sync.aligned.m16n8k16.row.col.f32.f16.f16.f32 "
        "{%0,%1,%2,%3}, {%4,%5,%6,%7}, {%8,%9}, {%0,%1,%2,%3};"
        : "+f"(d[0]), "+f"(d[1]), "+f"(d[2]), "+f"(d[3])
        : "r"(a[0]), "r"(a[1]), "r"(a[2]), "r"(a[3]), "r"(b0), "r"(b1));
}

// ---------------------------------------------------------------------------
// Wide GEMM (value projection): C(M,256) = A(M,256) @ Wh + bias, fp16 out.
// 512 threads, BM=128, BN=256, 3-stage cp.async ring (R8 best config).
// ---------------------------------------------------------------------------
__global__ __launch_bounds__(512, 1)
void gemm_vproj(const float* __restrict__ Af, const __half* __restrict__ Wh,
                const float* __restrict__ bias, __half* __restrict__ Cv, int M)
{
    constexpr int N = 256;
    constexpr int BM = 128, BK = 32, NIT = E_ / BK;  // 8
    constexpr int ST = 3;
    constexpr int AP = BK + 8;        // 40 halves
    constexpr int BP = 256 + 8;       // 264 halves
    constexpr int ASZ = BM * AP;      // 5120 halves
    constexpr int BSZ = BK * BP;      // 8448 halves

    extern __shared__ __half hs[];

    const int tid  = threadIdx.x;
    const int wid  = tid >> 5;
    const int lane = tid & 31;
    const int gid  = lane >> 2;
    const int tig  = lane & 3;

    const int row0 = blockIdx.x * BM;
    const int wr0  = (wid & 3) * 32;
    const int wc0  = (wid >> 2) * 64;

    const uint32_t sbase = smem_u32(hs);
    uint32_t sA[ST], sB[ST];
#pragma unroll
    for (int s = 0; s < ST; s++) {
        sA[s] = sbase + (uint32_t)(s * (ASZ + BSZ)) * 2;
        sB[s] = sA[s] + (uint32_t)ASZ * 2;
    }

    float acc[2][8][4];
#pragma unroll
    for (int mt = 0; mt < 2; mt++)
#pragma unroll
        for (int nt = 0; nt < 8; nt++)
#pragma unroll
            for (int i = 0; i < 4; i++) acc[mt][nt][i] = 0.f;

    float4 ar[2];

    auto ldgA = [&](int k0) {
#pragma unroll
        for (int i = 0; i < 2; i++) {
            int idx = tid + i * 512;
            int r = idx >> 3, c4 = idx & 7;
            ar[i] = *(const float4*)&Af[(size_t)(row0 + r) * E_ + k0 + c4 * 4];
        }
    };
    auto stsA = [&](int s) {
#pragma unroll
        for (int i = 0; i < 2; i++) {
            int idx = tid + i * 512;
            int r = idx >> 3, c4 = idx & 7;
            STS_V2(sA[s] + (uint32_t)(r * AP + c4 * 4) * 2,
                   pack_h2(ar[i].x, ar[i].y), pack_h2(ar[i].z, ar[i].w));
        }
    };
    auto asyncB = [&](int s, int k0) {
#pragma unroll
        for (int i = 0; i < 2; i++) {
            int chunk = tid + i * 512;
            int r = chunk >> 5, c8 = chunk & 31;
            CP_ASYNC16(sB[s] + (uint32_t)(r * BP + c8 * 8) * 2,
                       Wh + (size_t)(k0 + r) * N + c8 * 8);
        }
    };

    auto compute = [&](int s) {
#pragma unroll
        for (int ks = 0; ks < 2; ks++) {
            uint32_t a0[4], a1[4];
            const uint32_t arow = (uint32_t)(lane & 15);
            const uint32_t kof  = (uint32_t)(ks * 16 + (lane >> 4) * 8);
            LDMATRIX_X4(a0, sA[s] + (uint32_t)((wr0 + arow) * AP + kof) * 2);
            LDMATRIX_X4(a1, sA[s] + (uint32_t)((wr0 + 16 + arow) * AP + kof) * 2);
#pragma unroll
            for (int ntp = 0; ntp < 4; ntp++) {
                uint32_t bb[4];
                LDMATRIX_X4_T(bb, sB[s] + (uint32_t)((ks * 16 + (lane & 15)) * BP
                                   + wc0 + ntp * 16 + (lane >> 4) * 8) * 2);
                mma_f16(acc[0][2 * ntp],     a0, bb[0], bb[1]);
                mma_f16(acc[1][2 * ntp],     a1, bb[0], bb[1]);
                mma_f16(acc[0][2 * ntp + 1], a0, bb[2], bb[3]);
                mma_f16(acc[1][2 * ntp + 1], a1, bb[2], bb[3]);
            }
        }
    };

    ldgA(0);
    asyncB(0, 0); CP_COMMIT();
    stsA(0);
    ldgA(BK);
    asyncB(1, BK); CP_COMMIT();
    stsA(1);
    ldgA(2 * BK);

#pragma unroll
    for (int it = 0; it < NIT; it++) {
        if (it == NIT - 1) cp_wait<0>(); else cp_wait<1>();
        __syncthreads();
        if (it + 2 < NIT) {
            const int s2 = (it + 2) % ST;
            stsA(s2);
            asyncB(s2, (it + 2) * BK);
            CP_COMMIT();
            if (it + 3 < NIT) ldgA((it + 3) * BK);
        }
        compute(it % ST);
    }

    __half2* Ch = (__half2*)Cv;
#pragma unroll
    for (int mt = 0; mt < 2; mt++) {
#pragma unroll
        for (int nt = 0; nt < 8; nt++) {
            const int c = wc0 + nt * 8 + 2 * tig;
            const float bx = bias[c], by = bias[c + 1];
            const int r0 = row0 + wr0 + mt * 16 + gid;
            Ch[((size_t)r0 * N + c) >> 1] =
                __floats2half2_rn(acc[mt][nt][0] + bx, acc[mt][nt][1] + by);
            Ch[((size_t)(r0 + 8) * N + c) >> 1] =
                __floats2half2_rn(acc[mt][nt][2] + bx, acc[mt][nt][3] + by);
        }
    }
}

// ---------------------------------------------------------------------------
// Narrow GEMM (off/attn proj): 256 threads, BM=128, BN=96, 3-stage
// ---------------------------------------------------------------------------
__global__ __launch_bounds__(256, 2)
void gemm_oa(const float* __restrict__ A, const __half* __restrict__ Wh,
             const float* __restrict__ bias, float* __restrict__ C, int M)
{
    constexpr int N = 96;
    constexpr int BM = 128, BN = 96, BK = 32, NIT = E_ / BK;
    constexpr int ST = 3;
    constexpr int AP = BK + 8;
    constexpr int BP = BN + 8;
    constexpr int ASZ = BM * AP;
    constexpr int BSZ = BK * BP;
    constexpr int NTP = BN / 32;

    __shared__ __half hs[ST * (ASZ + BSZ)];

    const int tid  = threadIdx.x;
    const int wid  = tid >> 5;
    const int lane = tid & 31;
    const int gid  = lane >> 2;
    const int tig  = lane & 3;

    const int row0 = blockIdx.x * BM;
    const int wr0  = (wid & 3) * 32;
    const int wc0  = (wid >> 2) * (BN / 2);

    const uint32_t sbase = smem_u32(hs);
    uint32_t sA[ST], sB[ST];
#pragma unroll
    for (int s = 0; s < ST; s++) {
        sA[s] = sbase + (uint32_t)(s * (ASZ + BSZ)) * 2;
        sB[s] = sA[s] + (uint32_t)ASZ * 2;
    }

    float acc[2][BN / 16][4];
#pragma unroll
    for (int mt = 0; mt < 2; mt++)
#pragma unroll
        for (int nt = 0; nt < BN / 16; nt++)
#pragma unroll
            for (int i = 0; i < 4; i++) acc[mt][nt][i] = 0.f;

    float4 ar[4];

    auto ldgA = [&](int k0) {
#pragma unroll
        for (int i = 0; i < 4; i++) {
            int idx = tid + i * 256;
            int r = idx >> 3, c4 = idx & 7;
            ar[i] = *(const float4*)&A[(size_t)(row0 + r) * E_ + k0 + c4 * 4];
        }
    };
    auto stsA = [&](int s) {
#pragma unroll
        for (int i = 0; i < 4; i++) {
            int idx = tid + i * 256;
            int r = idx >> 3, c4 = idx & 7;
            STS_V2(sA[s] + (uint32_t)(r * AP + c4 * 4) * 2,
                   pack_h2(ar[i].x, ar[i].y), pack_h2(ar[i].z, ar[i].w));
        }
    };
    auto asyncB = [&](int s, int k0) {
        constexpr int BCH = BK * BN / 8;   // 384
#pragma unroll
        for (int i = 0; i < 2; i++) {
            int chunk = tid + i * 256;
            if (chunk < BCH) {
                int r = chunk / (BN / 8), c8 = chunk % (BN / 8);
                CP_ASYNC16(sB[s] + (uint32_t)(r * BP + c8 * 8) * 2,
                           Wh + (size_t)(k0 + r) * N + c8 * 8);
            }
        }
    };

    auto compute = [&](int s) {
#pragma unroll
        for (int ks = 0; ks < 2; ks++) {
            uint32_t a0[4], a1[4];
            const uint32_t arow = (uint32_t)(lane & 15);
            const uint32_t kof  = (uint32_t)(ks * 16 + (lane >> 4) * 8);
            LDMATRIX_X4(a0, sA[s] + (uint32_t)((wr0 + arow) * AP + kof) * 2);
            LDMATRIX_X4(a1, sA[s] + (uint32_t)((wr0 + 16 + arow) * AP + kof) * 2);
#pragma unroll
            for (int ntp = 0; ntp < NTP; ntp++) {
                uint32_t bb[4];
                LDMATRIX_X4_T(bb, sB[s] + (uint32_t)((ks * 16 + (lane & 15)) * BP
                                   + wc0 + ntp * 16 + (lane >> 4) * 8) * 2);
                mma_f16(acc[0][2 * ntp],     a0, bb[0], bb[1]);
                mma_f16(acc[1][2 * ntp],     a1, bb[0], bb[1]);
                mma_f16(acc[0][2 * ntp + 1], a0, bb[2], bb[3]);
                mma_f16(acc[1][2 * ntp + 1], a1, bb[2], bb[3]);
            }
        }
    };

    ldgA(0);
    asyncB(0, 0); CP_COMMIT();
    stsA(0);
    ldgA(BK);
    asyncB(1, BK); CP_COMMIT();
    stsA(1);
    ldgA(2 * BK);

#pragma unroll
    for (int it = 0; it < NIT; it++) {
        if (it == NIT - 1) cp_wait<0>(); else cp_wait<1>();
        __syncthreads();
        if (it + 2 < NIT) {
            const int s2 = (it + 2) % ST;
            stsA(s2);
            asyncB(s2, (it + 2) * BK);
            CP_COMMIT();
            if (it + 3 < NIT) ldgA((it + 3) * BK);
        }
        compute(it % ST);
    }

#pragma unroll
    for (int mt = 0; mt < 2; mt++) {
#pragma unroll
        for (int nt = 0; nt < BN / 16; nt++) {
            const int c = wc0 + nt * 8 + 2 * tig;
            const float bx = bias[c], by = bias[c + 1];
            const int r0 = row0 + wr0 + mt * 16 + gid;
            *(float2*)&C[(size_t)r0 * N + c] =
                make_float2(acc[mt][nt][0] + bx, acc[mt][nt][1] + by);
            *(float2*)&C[(size_t)(r0 + 8) * N + c] =
                make_float2(acc[mt][nt][2] + bx, acc[mt][nt][3] + by);
        }
    }
}

// ---------------------------------------------------------------------------
// FUSED sampler + out-projection.
// 512 threads, BM=128 queries/CTA. Warp w samples queries w*8..w*8+7 directly
// into the fp16 A smem tile (full 256-wide rows), then the CTA runs the
// B-ring ldmatrix/HMMA mainloop with no A gmem traffic. Epilogue adds bias
// + residual(query) and stores fp32 to d_out.
// ---------------------------------------------------------------------------
__global__ __launch_bounds__(512, 1)
void sample_outproj(const float* __restrict__ ref2d,
                    const __half* __restrict__ Wh,
                    const float* __restrict__ bias,
                    const float* __restrict__ Rq,
                    float* __restrict__ out)
{
    constexpr int N = 256;
    constexpr int BM = 128, BK = 32, NIT = E_ / BK;  // 8
    constexpr int ST = 3;
    constexpr int APF = 264;           // full A row in halves (256 + 8 pad)
    constexpr int BP  = 264;
    constexpr int ASZ = BM * APF;      // 33792 halves
    constexpr int BSZ = BK * BP;       // 8448 halves

    extern __shared__ __half hs[];     // ASZ + 3*BSZ = 59136 halves = 118272 B

    const int tid  = threadIdx.x;
    const int wid  = tid >> 5;
    const int lane = tid & 31;
    const int gid  = lane >> 2;
    const int tig  = lane & 3;

    const int row0 = blockIdx.x * BM;          // global query index base
    const int b    = row0 >> 13;               // batch (NQ_=8192)
    const int wr0  = (wid & 3) * 32;
    const int wc0  = (wid >> 4) * 64 + ((wid >> 2) & 3) * 0;  // see below

    // warp col mapping identical to gemm_vproj: wc0 = (wid>>2)*64
    const int wcol0 = (wid >> 2) * 64;

    const uint32_t sbase = smem_u32(hs);
    const uint32_t sAf = sbase;
    uint32_t sB[ST];
#pragma unroll
    for (int s = 0; s < ST; s++)
        sB[s] = sbase + (uint32_t)(ASZ + s * BSZ) * 2;

    auto asyncB = [&](int s, int k0) {
#pragma unroll
        for (int i = 0; i < 2; i++) {
            int chunk = tid + i * 512;
            int r = chunk >> 5, c8 = chunk & 31;
            CP_ASYNC16(sB[s] + (uint32_t)(r * BP + c8 * 8) * 2,
                       Wh + (size_t)(k0 + r) * N + c8 * 8);
        }
    };

    // prologue: B stages 0,1 in flight while we sample
    asyncB(0, 0);  CP_COMMIT();
    asyncB(1, BK); CP_COMMIT();

    // ---- sample phase: warp wid -> queries row0 + wid*8 .. +7 ----
    {
        const int c0 = (lane >> 2) * DH_ + (lane & 3) * 8;   // 8 channels
        const char* vb = (const char*)(g_v + (size_t)b * NV_ * E_ + c0);
#pragma unroll 1
        for (int i = 0; i < 8; i++) {
            const int bq = row0 + wid * 8 + i;

            const float rxs = fmaf(ref2d[(size_t)bq * 2 + 0], 128.f, -0.5f);
            const float rys = fmaf(ref2d[(size_t)bq * 2 + 1], 128.f, -0.5f);

            const float* qa = g_oa + (size_t)bq * 96;
            const int h = lane >> 2;
            const float4 lg = *(const float4*)&qa[64 + h * 4];
            const float e0 = __expf(lg.x), e1 = __expf(lg.y),
                        e2 = __expf(lg.z), e3 = __expf(lg.w);
            const float inv = __frcp_rn(e0 + e1 + e2 + e3);
            const float aw[P_] = { e0 * inv, e1 * inv, e2 * inv, e3 * inv };

            const float4 of0 = *(const float4*)&qa[h * 8];
            const float4 of1 = *(const float4*)&qa[h * 8 + 4];
            const float ox[P_] = { of0.x, of0.z, of1.x, of1.z };
            const float oy[P_] = { of0.y, of0.w, of1.y, of1.w };

            float acc[8] = {0.f,0.f,0.f,0.f,0.f,0.f,0.f,0.f};
#pragma unroll
            for (int p = 0; p < P_; p++) {
                const float x = rxs + ox[p];
                const float y = rys + oy[p];
                const float x0f = floorf(x), y0f = floorf(y);
                const int x0 = (int)x0f, y0 = (int)y0f;
                const int x1 = x0 + 1,  y1 = y0 + 1;
                const float wx1 = x - x0f, wx0 = 1.f - wx1;
                const float wy1 = y - y0f, wy0 = 1.f - wy1;

                const bool okx0 = (unsigned)x0 < (unsigned)WL_;
                const bool okx1 = (unsigned)x1 < (unsigned)WL_;
                const bool oky0 = (unsigned)y0 < (unsigned)HL_;
                const bool oky1 = (unsigned)y1 < (unsigned)HL_;
                const uint32_t bx0 = (uint32_t)min(max(x0, 0), WL_ - 1) << 9;
                const uint32_t bx1 = (uint32_t)min(max(x1, 0), WL_ - 1) << 9;
                const uint32_t by0 = (uint32_t)min(max(y0, 0), HL_ - 1) << 16;
                const uint32_t by1 = (uint32_t)min(max(y1, 0), HL_ - 1) << 16;

                const float awx0 = aw[p] * wx0, awx1 = aw[p] * wx1;
                const float    ws[4] = { (okx0 & oky0) ? awx0 * wy0 : 0.f,
                                         (okx1 & oky0) ? awx1 * wy0 : 0.f,
                                         (okx0 & oky1) ? awx0 * wy1 : 0.f,
                                         (okx1 & oky1) ? awx1 * wy1 : 0.f };
                const uint32_t os[4] = { by0 + bx0, by0 + bx1, by1 + bx0, by1 + bx1 };

#pragma unroll
                for (int cnr = 0; cnr < 4; cnr++) {
                    const float w = ws[cnr];
                    const uint4 raw = *(const uint4*)(vb + os[cnr]);
                    const float2 f0 = __half22float2(*(const __half2*)&raw.x);
                    const float2 f1 = __half22float2(*(const __half2*)&raw.y);
                    const float2 f2 = __half22float2(*(const __half2*)&raw.z);
                    const float2 f3 = __half22float2(*(const __half2*)&raw.w);
                    acc[0] = fmaf(w, f0.x, acc[0]); acc[1] = fmaf(w, f0.y, acc[1]);
                    acc[2] = fmaf(w, f1.x, acc[2]); acc[3] = fmaf(w, f1.y, acc[3]);
                    acc[4] = fmaf(w, f2.x, acc[4]); acc[5] = fmaf(w, f2.y, acc[5]);
                    acc[6] = fmaf(w, f3.x, acc[6]); acc[7] = fmaf(w, f3.y, acc[7]);
                }
            }

            STS_V4(sAf + (uint32_t)((wid * 8 + i) * APF + c0) * 2,
                   pack_h2(acc[0], acc[1]), pack_h2(acc[2], acc[3]),
                   pack_h2(acc[4], acc[5]), pack_h2(acc[6], acc[7]));
        }
    }

    // ---- GEMM phase ----
    float dacc[2][8][4];
#pragma unroll
    for (int mt = 0; mt < 2; mt++)
#pragma unroll
        for (int nt = 0; nt < 8; nt++)
#pragma unroll
            for (int i = 0; i < 4; i++) dacc[mt][nt][i] = 0.f;

#pragma unroll
    for (int it = 0; it < NIT; it++) {
        if (it == NIT - 1) cp_wait<0>(); else cp_wait<1>();
        __syncthreads();   // A tile ready (it==0) / B slot WAR (it>0)
        if (it + 2 < NIT) {
            asyncB((it + 2) % ST, (it + 2) * BK);
            CP_COMMIT();
        }
        const int s = it % ST;
#pragma unroll
        for (int ks = 0; ks < 2; ks++) {
            uint32_t a0[4], a1[4];
            const uint32_t arow = (uint32_t)(lane & 15);
            const uint32_t kof  = (uint32_t)(it * BK + ks * 16 + (lane >> 4) * 8);
            LDMATRIX_X4(a0, sAf + (uint32_t)((wr0 + arow) * APF + kof) * 2);
            LDMATRIX_X4(a1, sAf + (uint32_t)((wr0 + 16 + arow) * APF + kof) * 2);
#pragma unroll
            for (int ntp = 0; ntp < 4; ntp++) {
                uint32_t bb[4];
                LDMATRIX_X4_T(bb, sB[s] + (uint32_t)((ks * 16 + (lane & 15)) * BP
                                   + wcol0 + ntp * 16 + (lane >> 4) * 8) * 2);
                mma_f16(dacc[0][2 * ntp],     a0, bb[0], bb[1]);
                mma_f16(dacc[1][2 * ntp],     a1, bb[0], bb[1]);
                mma_f16(dacc[0][2 * ntp + 1], a0, bb[2], bb[3]);
                mma_f16(dacc[1][2 * ntp + 1], a1, bb[2], bb[3]);
            }
        }
    }

    // ---- epilogue: bias + residual + fp32 store ----
#pragma unroll
    for (int mt = 0; mt < 2; mt++) {
#pragma unroll
        for (int nt = 0; nt < 8; nt++) {
            const int c = wcol0 + nt * 8 + 2 * tig;
            const float bx = bias[c], by = bias[c + 1];
            const int r0 = row0 + wr0 + mt * 16 + gid;
            const float2 rv0 = *(const float2*)&Rq[(size_t)r0 * N + c];
            const float2 rv1 = *(const float2*)&Rq[(size_t)(r0 + 8) * N + c];
            *(float2*)&out[(size_t)r0 * N + c] =
                make_float2(dacc[mt][nt][0] + bx + rv0.x,
                            dacc[mt][nt][1] + by + rv0.y);
            *(float2*)&out[(size_t)(r0 + 8) * N + c] =
                make_float2(dacc[mt][nt][2] + bx + rv1.x,
                            dacc[mt][nt][3] + by + rv1.y);
        }
    }
    (void)wc0;
}

// ---------------------------------------------------------------------------
// Weight prep
// ---------------------------------------------------------------------------
__global__ void prep_weights(const float* __restrict__ Wv, const float* __restrict__ Wu,
                             const float* __restrict__ Wo, const float* __restrict__ Wa,
                             const float* __restrict__ bo, const float* __restrict__ ba)
{
    const int t = blockIdx.x * blockDim.x + threadIdx.x;
    if (t < E_ * E_) {
        g_wv16[t] = __float2half_rn(Wv[t]);
        g_wu16[t] = __float2half_rn(Wu[t]);
    }
    if (t < E_ * 96) {
        const int k = t / 96, n = t % 96;
        g_wc16[t] = __float2half_rn(n < 64 ? Wo[k * 64 + n] : Wa[k * 32 + (n - 64)]);
    }
    if (t < 96) g_bcat[t] = (t < 64) ? bo[t] : ba[t - 64];
}

// ---------------------------------------------------------------------------
extern "C" void kernel_launch(void* const* d_in, const int* in_sizes, int n_in,
                              void* d_out, int out_size)
{
    const float* query  = (const float*)d_in[0];
    const float* value  = (const float*)d_in[1];
    const float* ref2d  = (const float*)d_in[2];
    const float* W_off  = (const float*)d_in[4];
    const float* b_off  = (const float*)d_in[5];
    const float* W_attn = (const float*)d_in[6];
    const float* b_attn = (const float*)d_in[7];
    const float* W_val  = (const float*)d_in[8];
    const float* b_val  = (const float*)d_in[9];
    const float* W_out  = (const float*)d_in[10];
    const float* b_out  = (const float*)d_in[11];
    float* out = (float*)d_out;

    void *v_ptr, *oa_ptr, *wv_ptr, *wu_ptr, *wc_ptr, *bc_ptr;
    cudaGetSymbolAddress(&v_ptr,  g_v);
    cudaGetSymbolAddress(&oa_ptr, g_oa);
    cudaGetSymbolAddress(&wv_ptr, g_wv16);
    cudaGetSymbolAddress(&wu_ptr, g_wu16);
    cudaGetSymbolAddress(&wc_ptr, g_wc16);
    cudaGetSymbolAddress(&bc_ptr, g_bcat);

    const int vp_smem = 3 * (128 * 40 + 32 * 264) * 2;        // 81408 B
    const int so_smem = (128 * 264 + 3 * 32 * 264) * 2;       // 118272 B
    cudaFuncSetAttribute((const void*)gemm_vproj,
                         cudaFuncAttributeMaxDynamicSharedMemorySize, vp_smem);
    cudaFuncSetAttribute((const void*)sample_outproj,
                         cudaFuncAttributeMaxDynamicSharedMemorySize, so_smem);

    const int Mv = B_ * NV_;   // 131072
    const int Mq = B_ * NQ_;   // 65536

    // 0) weight prep
    prep_weights<<<256, 256>>>(W_val, W_out, W_off, W_attn, b_off, b_attn);

    // 1) value projection -> fp16 g_v
    gemm_vproj<<<Mv / 128, 512, vp_smem>>>(value, (const __half*)wv_ptr, b_val,
                                           (__half*)v_ptr, Mv);
    // 2) fused offset+attn projection -> fp32 g_oa
    gemm_oa<<<Mq / 128, 256>>>(query, (const __half*)wc_ptr,
                               (const float*)bc_ptr, (float*)oa_ptr, Mq);
    // 3) FUSED sampling + output projection + bias + residual -> fp32 d_out
    sample_outproj<<<Mq / 128, 512, so_smem>>>(ref2d, (const __half*)wu_ptr,
                                               b_out, query, out);
}

// round 17
// speedup vs baseline: 1.2609x; 1.0488x over previous
#include <cuda_runtime.h>
#include <cuda_fp16.h>
#include <cstdint>
#include <cmath>

// Problem constants (fixed by setup_inputs)
#define B_   8
#define NQ_  8192
#define E_   256
#define HN_  8
#define P_   4
#define DH_  32
#define NV_  16384   // 128*128
#define WL_  128
#define HL_  128

// Scratch (no cudaMalloc allowed)
__device__ __half g_v [(size_t)B_ * NV_ * E_];           // projected value, fp16
__device__ float  g_oa[(size_t)B_ * NQ_ * 96];           // [off(64) | attn(32)] per query
__device__ __half g_o [(size_t)B_ * NQ_ * E_];           // sampled output, fp16
__device__ __half g_wv16[E_ * E_];                       // W_val  fp16 [k][n]
__device__ __half g_wu16[E_ * E_];                       // W_out  fp16 [k][n]
__device__ __half g_wc16[E_ * 96];                       // [W_off|W_attn] fp16 [k][n]
__device__ float  g_bcat[96];

// ---------------------------------------------------------------------------
// PTX helpers
// ---------------------------------------------------------------------------
#define CP_ASYNC16(saddr, gaddr) \
    asm volatile("cp.async.cg.shared.global [%0], [%1], 16;" :: "r"(saddr), "l"(gaddr) : "memory")
#define CP_COMMIT() asm volatile("cp.async.commit_group;" ::: "memory")
template<int N>
__device__ __forceinline__ void cp_wait() {
    asm volatile("cp.async.wait_group %0;" :: "n"(N) : "memory");
}

__device__ __forceinline__ uint32_t smem_u32(const void* p) {
    uint32_t a;
    asm("{ .reg .u64 t; cvta.to.shared.u64 t, %1; cvt.u32.u64 %0, t; }" : "=r"(a) : "l"(p));
    return a;
}

__device__ __forceinline__ uint32_t pack_h2(float x, float y) {
    uint32_t r;
    asm("cvt.rn.f16x2.f32 %0, %2, %1;" : "=r"(r) : "f"(x), "f"(y));
    return r;
}

#define LDMATRIX_X4(r, addr) \
    asm volatile("ldmatrix.sync.aligned.m8n8.x4.shared.b16 {%0,%1,%2,%3}, [%4];" \
        : "=r"((r)[0]), "=r"((r)[1]), "=r"((r)[2]), "=r"((r)[3]) : "r"(addr))
#define LDMATRIX_X4_T(r, addr) \
    asm volatile("ldmatrix.sync.aligned.m8n8.x4.trans.shared.b16 {%0,%1,%2,%3}, [%4];" \
        : "=r"((r)[0]), "=r"((r)[1]), "=r"((r)[2]), "=r"((r)[3]) : "r"(addr))
#define STS_V2(addr, x, y) \
    asm volatile("st.shared.v2.b32 [%0], {%1,%2};" :: "r"(addr), "r"(x), "r"(y) : "memory")

__device__ __forceinline__ void mma_f16(float d[4], const uint32_t a[4],
                                        uint32_t b0, uint32_t b1) {
    asm volatile(
        "mma.sync.aligned.m16n8k16.row.col.f32.f16.f16.f32 "
        "{%0,%1,%2,%3}, {%4,%5,%6,%7}, {%8,%9}, {%0,%1,%2,%3};"
        : "+f"(d[0]), "+f"(d[1]), "+f"(d[2]), "+f"(d[3])
        : "r"(a[0]), "r"(a[1]), "r"(a[2]), "r"(a[3]), "r"(b0), "r"(b1));
}

// ---------------------------------------------------------------------------
// Wide GEMM: C(M,256) = A(M,256) @ Wh(256,256) + bias (+R)
// 512 threads, BM=128, BN=256, 3-stage cp.async ring (R8 best config).
// ---------------------------------------------------------------------------
template<bool AHALF, bool RESID, bool OHALF>
__global__ __launch_bounds__(512, 1)
void gemm_wide(const void* __restrict__ Av, const __half* __restrict__ Wh,
               const float* __restrict__ bias, const float* __restrict__ R,
               void* __restrict__ Cv, int M)
{
    constexpr int N = 256;
    constexpr int BM = 128, BK = 32, NIT = E_ / BK;  // 8
    constexpr int ST = 3;
    constexpr int AP = BK + 8;        // 40 halves
    constexpr int BP = 256 + 8;       // 264 halves
    constexpr int ASZ = BM * AP;      // 5120 halves
    constexpr int BSZ = BK * BP;      // 8448 halves

    extern __shared__ __half hs[];

    const int tid  = threadIdx.x;
    const int wid  = tid >> 5;
    const int lane = tid & 31;
    const int gid  = lane >> 2;
    const int tig  = lane & 3;

    const int row0 = blockIdx.x * BM;
    const int wr0  = (wid & 3) * 32;
    const int wc0  = (wid >> 2) * 64;

    const uint32_t sbase = smem_u32(hs);
    uint32_t sA[ST], sB[ST];
#pragma unroll
    for (int s = 0; s < ST; s++) {
        sA[s] = sbase + (uint32_t)(s * (ASZ + BSZ)) * 2;
        sB[s] = sA[s] + (uint32_t)ASZ * 2;
    }

    const float*  Af = (const float*)Av;
    const __half* Ah = (const __half*)Av;

    float acc[2][8][4];
#pragma unroll
    for (int mt = 0; mt < 2; mt++)
#pragma unroll
        for (int nt = 0; nt < 8; nt++)
#pragma unroll
            for (int i = 0; i < 4; i++) acc[mt][nt][i] = 0.f;

    float4 ar[2];

    auto ldgA = [&](int k0) {
        if (!AHALF) {
#pragma unroll
            for (int i = 0; i < 2; i++) {
                int idx = tid + i * 512;
                int r = idx >> 3, c4 = idx & 7;
                ar[i] = *(const float4*)&Af[(size_t)(row0 + r) * E_ + k0 + c4 * 4];
            }
        }
    };
    auto stsA = [&](int s) {
        if (!AHALF) {
#pragma unroll
            for (int i = 0; i < 2; i++) {
                int idx = tid + i * 512;
                int r = idx >> 3, c4 = idx & 7;
                STS_V2(sA[s] + (uint32_t)(r * AP + c4 * 4) * 2,
                       pack_h2(ar[i].x, ar[i].y), pack_h2(ar[i].z, ar[i].w));
            }
        }
    };
    auto asyncA = [&](int s, int k0) {
        if (AHALF) {
            int r = tid >> 2, c8 = tid & 3;
            CP_ASYNC16(sA[s] + (uint32_t)(r * AP + c8 * 8) * 2,
                       Ah + (size_t)(row0 + r) * E_ + k0 + c8 * 8);
        }
    };
    auto asyncB = [&](int s, int k0) {
#pragma unroll
        for (int i = 0; i < 2; i++) {
            int chunk = tid + i * 512;
            int r = chunk >> 5, c8 = chunk & 31;
            CP_ASYNC16(sB[s] + (uint32_t)(r * BP + c8 * 8) * 2,
                       Wh + (size_t)(k0 + r) * N + c8 * 8);
        }
    };

    auto compute = [&](int s) {
#pragma unroll
        for (int ks = 0; ks < 2; ks++) {
            uint32_t a0[4], a1[4];
            const uint32_t arow = (uint32_t)(lane & 15);
            const uint32_t kof  = (uint32_t)(ks * 16 + (lane >> 4) * 8);
            LDMATRIX_X4(a0, sA[s] + (uint32_t)((wr0 + arow) * AP + kof) * 2);
            LDMATRIX_X4(a1, sA[s] + (uint32_t)((wr0 + 16 + arow) * AP + kof) * 2);
#pragma unroll
            for (int ntp = 0; ntp < 4; ntp++) {
                uint32_t bb[4];
                LDMATRIX_X4_T(bb, sB[s] + (uint32_t)((ks * 16 + (lane & 15)) * BP
                                   + wc0 + ntp * 16 + (lane >> 4) * 8) * 2);
                mma_f16(acc[0][2 * ntp],     a0, bb[0], bb[1]);
                mma_f16(acc[1][2 * ntp],     a1, bb[0], bb[1]);
                mma_f16(acc[0][2 * ntp + 1], a0, bb[2], bb[3]);
                mma_f16(acc[1][2 * ntp + 1], a1, bb[2], bb[3]);
            }
        }
    };

    // ---- prologue ----
    ldgA(0);
    asyncA(0, 0); asyncB(0, 0); CP_COMMIT();
    stsA(0);
    ldgA(BK);
    asyncA(1, BK); asyncB(1, BK); CP_COMMIT();
    stsA(1);
    ldgA(2 * BK);

    // ---- mainloop ----
#pragma unroll
    for (int it = 0; it < NIT; it++) {
        if (it == NIT - 1) cp_wait<0>(); else cp_wait<1>();
        __syncthreads();
        if (it + 2 < NIT) {
            const int s2 = (it + 2) % ST;
            stsA(s2);
            asyncA(s2, (it + 2) * BK);
            asyncB(s2, (it + 2) * BK);
            CP_COMMIT();
            if (it + 3 < NIT) ldgA((it + 3) * BK);
        }
        compute(it % ST);
    }

    // ---- epilogue ----
    float*   Cf = (float*)Cv;
    __half2* Ch = (__half2*)Cv;
#pragma unroll
    for (int mt = 0; mt < 2; mt++) {
#pragma unroll
        for (int nt = 0; nt < 8; nt++) {
            const int c = wc0 + nt * 8 + 2 * tig;
            const float bx = bias[c], by = bias[c + 1];
            const int r0 = row0 + wr0 + mt * 16 + gid;
            float2 o0 = { acc[mt][nt][0] + bx, acc[mt][nt][1] + by };
            float2 o1 = { acc[mt][nt][2] + bx, acc[mt][nt][3] + by };
            if (RESID) {
                const float2 rv0 = *(const float2*)&R[(size_t)r0 * N + c];
                const float2 rv1 = *(const float2*)&R[(size_t)(r0 + 8) * N + c];
                o0.x += rv0.x; o0.y += rv0.y;
                o1.x += rv1.x; o1.y += rv1.y;
            }
            if (OHALF) {
                Ch[((size_t)r0 * N + c) >> 1]       = __floats2half2_rn(o0.x, o0.y);
                Ch[((size_t)(r0 + 8) * N + c) >> 1] = __floats2half2_rn(o1.x, o1.y);
            } else {
                *(float2*)&Cf[(size_t)r0 * N + c]       = o0;
                *(float2*)&Cf[(size_t)(r0 + 8) * N + c] = o1;
            }
        }
    }
}

// ---------------------------------------------------------------------------
// Narrow GEMM (off/attn proj): 256 threads, BM=128, BN=96, 3-stage
// ---------------------------------------------------------------------------
__global__ __launch_bounds__(256, 2)
void gemm_oa(const float* __restrict__ A, const __half* __restrict__ Wh,
             const float* __restrict__ bias, float* __restrict__ C, int M)
{
    constexpr int N = 96;
    constexpr int BM = 128, BN = 96, BK = 32, NIT = E_ / BK;
    constexpr int ST = 3;
    constexpr int AP = BK + 8;
    constexpr int BP = BN + 8;
    constexpr int ASZ = BM * AP;
    constexpr int BSZ = BK * BP;
    constexpr int NTP = BN / 32;

    __shared__ __half hs[ST * (ASZ + BSZ)];

    const int tid  = threadIdx.x;
    const int wid  = tid >> 5;
    const int lane = tid & 31;
    const int gid  = lane >> 2;
    const int tig  = lane & 3;

    const int row0 = blockIdx.x * BM;
    const int wr0  = (wid & 3) * 32;
    const int wc0  = (wid >> 2) * (BN / 2);

    const uint32_t sbase = smem_u32(hs);
    uint32_t sA[ST], sB[ST];
#pragma unroll
    for (int s = 0; s < ST; s++) {
        sA[s] = sbase + (uint32_t)(s * (ASZ + BSZ)) * 2;
        sB[s] = sA[s] + (uint32_t)ASZ * 2;
    }

    float acc[2][BN / 16][4];
#pragma unroll
    for (int mt = 0; mt < 2; mt++)
#pragma unroll
        for (int nt = 0; nt < BN / 16; nt++)
#pragma unroll
            for (int i = 0; i < 4; i++) acc[mt][nt][i] = 0.f;

    float4 ar[4];

    auto ldgA = [&](int k0) {
#pragma unroll
        for (int i = 0; i < 4; i++) {
            int idx = tid + i * 256;
            int r = idx >> 3, c4 = idx & 7;
            ar[i] = *(const float4*)&A[(size_t)(row0 + r) * E_ + k0 + c4 * 4];
        }
    };
    auto stsA = [&](int s) {
#pragma unroll
        for (int i = 0; i < 4; i++) {
            int idx = tid + i * 256;
            int r = idx >> 3, c4 = idx & 7;
            STS_V2(sA[s] + (uint32_t)(r * AP + c4 * 4) * 2,
                   pack_h2(ar[i].x, ar[i].y), pack_h2(ar[i].z, ar[i].w));
        }
    };
    auto asyncB = [&](int s, int k0) {
        constexpr int BCH = BK * BN / 8;   // 384
#pragma unroll
        for (int i = 0; i < 2; i++) {
            int chunk = tid + i * 256;
            if (chunk < BCH) {
                int r = chunk / (BN / 8), c8 = chunk % (BN / 8);
                CP_ASYNC16(sB[s] + (uint32_t)(r * BP + c8 * 8) * 2,
                           Wh + (size_t)(k0 + r) * N + c8 * 8);
            }
        }
    };

    auto compute = [&](int s) {
#pragma unroll
        for (int ks = 0; ks < 2; ks++) {
            uint32_t a0[4], a1[4];
            const uint32_t arow = (uint32_t)(lane & 15);
            const uint32_t kof  = (uint32_t)(ks * 16 + (lane >> 4) * 8);
            LDMATRIX_X4(a0, sA[s] + (uint32_t)((wr0 + arow) * AP + kof) * 2);
            LDMATRIX_X4(a1, sA[s] + (uint32_t)((wr0 + 16 + arow) * AP + kof) * 2);
#pragma unroll
            for (int ntp = 0; ntp < NTP; ntp++) {
                uint32_t bb[4];
                LDMATRIX_X4_T(bb, sB[s] + (uint32_t)((ks * 16 + (lane & 15)) * BP
                                   + wc0 + ntp * 16 + (lane >> 4) * 8) * 2);
                mma_f16(acc[0][2 * ntp],     a0, bb[0], bb[1]);
                mma_f16(acc[1][2 * ntp],     a1, bb[0], bb[1]);
                mma_f16(acc[0][2 * ntp + 1], a0, bb[2], bb[3]);
                mma_f16(acc[1][2 * ntp + 1], a1, bb[2], bb[3]);
            }
        }
    };

    ldgA(0);
    asyncB(0, 0); CP_COMMIT();
    stsA(0);
    ldgA(BK);
    asyncB(1, BK); CP_COMMIT();
    stsA(1);
    ldgA(2 * BK);

#pragma unroll
    for (int it = 0; it < NIT; it++) {
        if (it == NIT - 1) cp_wait<0>(); else cp_wait<1>();
        __syncthreads();
        if (it + 2 < NIT) {
            const int s2 = (it + 2) % ST;
            stsA(s2);
            asyncB(s2, (it + 2) * BK);
            CP_COMMIT();
            if (it + 3 < NIT) ldgA((it + 3) * BK);
        }
        compute(it % ST);
    }

#pragma unroll
    for (int mt = 0; mt < 2; mt++) {
#pragma unroll
        for (int nt = 0; nt < BN / 16; nt++) {
            const int c = wc0 + nt * 8 + 2 * tig;
            const float bx = bias[c], by = bias[c + 1];
            const int r0 = row0 + wr0 + mt * 16 + gid;
            *(float2*)&C[(size_t)r0 * N + c] =
                make_float2(acc[mt][nt][0] + bx, acc[mt][nt][1] + by);
            *(float2*)&C[(size_t)(r0 + 8) * N + c] =
                make_float2(acc[mt][nt][2] + bx, acc[mt][nt][3] + by);
        }
    }
}

// ---------------------------------------------------------------------------
// Weight prep
// ---------------------------------------------------------------------------
__global__ void prep_weights(const float* __restrict__ Wv, const float* __restrict__ Wu,
                             const float* __restrict__ Wo, const float* __restrict__ Wa,
                             const float* __restrict__ bo, const float* __restrict__ ba)
{
    const int t = blockIdx.x * blockDim.x + threadIdx.x;
    if (t < E_ * E_) {
        g_wv16[t] = __float2half_rn(Wv[t]);
        g_wu16[t] = __float2half_rn(Wu[t]);
    }
    if (t < E_ * 96) {
        const int k = t / 96, n = t % 96;
        g_wc16[t] = __float2half_rn(n < 64 ? Wo[k * 64 + n] : Wa[k * 32 + (n - 64)]);
    }
    if (t < 96) g_bcat[t] = (t < 64) ? bo[t] : ba[t - 64];
}

// ---------------------------------------------------------------------------
// Sampling: ONE warp per (b,q); lane = 8 channels (uint4 corner loads).
// ---------------------------------------------------------------------------
__global__ __launch_bounds__(256)
void sample_kernel(const float* __restrict__ ref2d)
{
    const int gtid = blockIdx.x * blockDim.x + threadIdx.x;
    const int bq   = gtid >> 5;
    const int lane = gtid & 31;
    if (bq >= B_ * NQ_) return;
    const int b = bq >> 13;                     // NQ_ = 8192

    const int h  = lane >> 2;                   // head 0..7
    const int c0 = h * DH_ + (lane & 3) * 8;    // channel base (8 ch)

    const float rxs = fmaf(ref2d[(size_t)bq * 2 + 0], 128.f, -0.5f);
    const float rys = fmaf(ref2d[(size_t)bq * 2 + 1], 128.f, -0.5f);

    const float* qa = g_oa + (size_t)bq * 96;
    const float4 lg = *(const float4*)&qa[64 + h * 4];
    const float e0 = __expf(lg.x), e1 = __expf(lg.y),
                e2 = __expf(lg.z), e3 = __expf(lg.w);
    const float inv = __frcp_rn(e0 + e1 + e2 + e3);
    const float aw[P_] = { e0 * inv, e1 * inv, e2 * inv, e3 * inv };

    const float4 of0 = *(const float4*)&qa[h * 8];
    const float4 of1 = *(const float4*)&qa[h * 8 + 4];
    const float ox[P_] = { of0.x, of0.z, of1.x, of1.z };
    const float oy[P_] = { of0.y, of0.w, of1.y, of1.w };

    const char* vb = (const char*)(g_v + (size_t)b * NV_ * E_ + c0);

    float acc[8] = {0.f, 0.f, 0.f, 0.f, 0.f, 0.f, 0.f, 0.f};
#pragma unroll
    for (int p = 0; p < P_; p++) {
        const float x = rxs + ox[p];
        const float y = rys + oy[p];
        const float x0f = floorf(x), y0f = floorf(y);
        const int x0 = (int)x0f, y0 = (int)y0f;
        const int x1 = x0 + 1,  y1 = y0 + 1;
        const float wx1 = x - x0f, wx0 = 1.f - wx1;
        const float wy1 = y - y0f, wy0 = 1.f - wy1;

        const bool okx0 = (unsigned)x0 < (unsigned)WL_;
        const bool okx1 = (unsigned)x1 < (unsigned)WL_;
        const bool oky0 = (unsigned)y0 < (unsigned)HL_;
        const bool oky1 = (unsigned)y1 < (unsigned)HL_;
        const uint32_t bx0 = (uint32_t)min(max(x0, 0), WL_ - 1) << 9;
        const uint32_t bx1 = (uint32_t)min(max(x1, 0), WL_ - 1) << 9;
        const uint32_t by0 = (uint32_t)min(max(y0, 0), HL_ - 1) << 16;
        const uint32_t by1 = (uint32_t)min(max(y1, 0), HL_ - 1) << 16;

        const float awx0 = aw[p] * wx0, awx1 = aw[p] * wx1;
        const float    ws[4] = { (okx0 & oky0) ? awx0 * wy0 : 0.f,
                                 (okx1 & oky0) ? awx1 * wy0 : 0.f,
                                 (okx0 & oky1) ? awx0 * wy1 : 0.f,
                                 (okx1 & oky1) ? awx1 * wy1 : 0.f };
        const uint32_t os[4] = { by0 + bx0, by0 + bx1, by1 + bx0, by1 + bx1 };

#pragma unroll
        for (int cnr = 0; cnr < 4; cnr++) {
            const float w = ws[cnr];
            const uint4 raw = *(const uint4*)(vb + os[cnr]);
            const float2 f0 = __half22float2(*(const __half2*)&raw.x);
            const float2 f1 = __half22float2(*(const __half2*)&raw.y);
            const float2 f2 = __half22float2(*(const __half2*)&raw.z);
            const float2 f3 = __half22float2(*(const __half2*)&raw.w);
            acc[0] = fmaf(w, f0.x, acc[0]); acc[1] = fmaf(w, f0.y, acc[1]);
            acc[2] = fmaf(w, f1.x, acc[2]); acc[3] = fmaf(w, f1.y, acc[3]);
            acc[4] = fmaf(w, f2.x, acc[4]); acc[5] = fmaf(w, f2.y, acc[5]);
            acc[6] = fmaf(w, f3.x, acc[6]); acc[7] = fmaf(w, f3.y, acc[7]);
        }
    }

    uint4 outp;
    outp.x = pack_h2(acc[0], acc[1]);
    outp.y = pack_h2(acc[2], acc[3]);
    outp.z = pack_h2(acc[4], acc[5]);
    outp.w = pack_h2(acc[6], acc[7]);
    *(uint4*)&g_o[(size_t)bq * E_ + c0] = outp;
}

// ---------------------------------------------------------------------------
extern "C" void kernel_launch(void* const* d_in, const int* in_sizes, int n_in,
                              void* d_out, int out_size)
{
    const float* query  = (const float*)d_in[0];
    const float* value  = (const float*)d_in[1];
    const float* ref2d  = (const float*)d_in[2];
    const float* W_off  = (const float*)d_in[4];
    const float* b_off  = (const float*)d_in[5];
    const float* W_attn = (const float*)d_in[6];
    const float* b_attn = (const float*)d_in[7];
    const float* W_val  = (const float*)d_in[8];
    const float* b_val  = (const float*)d_in[9];
    const float* W_out  = (const float*)d_in[10];
    const float* b_out  = (const float*)d_in[11];
    float* out = (float*)d_out;

    void *v_ptr, *oa_ptr, *o_ptr, *wv_ptr, *wu_ptr, *wc_ptr, *bc_ptr;
    cudaGetSymbolAddress(&v_ptr,  g_v);
    cudaGetSymbolAddress(&oa_ptr, g_oa);
    cudaGetSymbolAddress(&o_ptr,  g_o);
    cudaGetSymbolAddress(&wv_ptr, g_wv16);
    cudaGetSymbolAddress(&wu_ptr, g_wu16);
    cudaGetSymbolAddress(&wc_ptr, g_wc16);
    cudaGetSymbolAddress(&bc_ptr, g_bcat);

    // one-time side stream + 2 events (single fork/join)
    static cudaStream_t s2 = nullptr;
    static cudaEvent_t  eP = nullptr, eV = nullptr;
    if (!s2) {
        cudaStreamCreateWithFlags(&s2, cudaStreamNonBlocking);
        cudaEventCreateWithFlags(&eP, cudaEventDisableTiming);
        cudaEventCreateWithFlags(&eV, cudaEventDisableTiming);
    }

    const int wide_smem = 3 * (128 * 40 + 32 * 264) * 2;   // 81408 B
    cudaFuncSetAttribute((const void*)gemm_wide<false, false, true>,
                         cudaFuncAttributeMaxDynamicSharedMemorySize, wide_smem);
    cudaFuncSetAttribute((const void*)gemm_wide<true, true, false>,
                         cudaFuncAttributeMaxDynamicSharedMemorySize, wide_smem);

    const int Mv = B_ * NV_;   // 131072
    const int Mq = B_ * NQ_;   // 65536

    // 0) weight prep on the default (capture) stream
    prep_weights<<<256, 256>>>(W_val, W_out, W_off, W_attn, b_off, b_attn);

    // fork: full value projection on side stream
    cudaEventRecord(eP, 0);
    cudaStreamWaitEvent(s2, eP, 0);
    gemm_wide<false, false, true><<<Mv / 128, 512, wide_smem, s2>>>(
        value, (const __half*)wv_ptr, b_val, nullptr, v_ptr, Mv);
    cudaEventRecord(eV, s2);

    // default stream: fused offset+attn projection (overlaps vproj)
    gemm_oa<<<Mq / 128, 256>>>(query, (const __half*)wc_ptr,
                               (const float*)bc_ptr, (float*)oa_ptr, Mq);

    // join: sample needs g_v (vproj) + g_oa (oa)
    cudaStreamWaitEvent(0, eV, 0);
    sample_kernel<<<(Mq * 32) / 256, 256>>>(ref2d);

    // output projection + bias + residual -> fp32 d_out
    gemm_wide<true, true, false><<<Mq / 128, 512, wide_smem>>>(
        o_ptr, (const __half*)wu_ptr, b_out, query, out, Mq);
}